// round 6
// baseline (speedup 1.0000x reference)
#include <cuda_runtime.h>

#define BATCH 2
#define SEQ   2048
#define EMB   128
#define NH    8
#define HD    16
#define NROWS (BATCH*SEQ)
#define KT    128        // keys per smem tile
#define NKV   4          // KV splits across CTAs
#define KEYS_PER_CTA (SEQ/NKV)   // 512
#define PREC  20         // floats per partial record (16 acc, m, l, pad)

// Scratch for head-split Q/K/V in [b][h][s][d] layout (d contiguous, 64B rows).
__device__ float g_Q[BATCH*NH*SEQ*HD];
__device__ float g_K[BATCH*NH*SEQ*HD];
__device__ float g_V[BATCH*NH*SEQ*HD];
// Partials: [query_row(32768)][kv_split(4)][PREC]
__device__ float g_part[BATCH*NH*SEQ*NKV*PREC];

typedef unsigned long long u64;

__device__ __forceinline__ u64 pack2(float lo, float hi){
    u64 r; asm("mov.b64 %0, {%1, %2};" : "=l"(r) : "f"(lo), "f"(hi)); return r;
}
__device__ __forceinline__ void unpack2(u64 v, float& a, float& b){
    asm("mov.b64 {%0, %1}, %2;" : "=f"(a), "=f"(b) : "l"(v));
}
__device__ __forceinline__ u64 fma2(u64 a, u64 b, u64 c){
    u64 d; asm("fma.rn.f32x2 %0, %1, %2, %3;" : "=l"(d) : "l"(a), "l"(b), "l"(c)); return d;
}
__device__ __forceinline__ u64 mul2(u64 a, u64 b){
    u64 d; asm("mul.rn.f32x2 %0, %1, %2;" : "=l"(d) : "l"(a), "l"(b)); return d;
}
__device__ __forceinline__ float ex2f(float x){
    float y; asm("ex2.approx.ftz.f32 %0, %1;" : "=f"(y) : "f"(x)); return y;
}

// ---------------------------------------------------------------------------
// Kernel 1: fused QKV projection + head split (unchanged).
// ---------------------------------------------------------------------------
__global__ __launch_bounds__(256) void qkv_kernel(
    const float* __restrict__ X,
    const float* __restrict__ Wq, const float* __restrict__ Wk,
    const float* __restrict__ Wv)
{
    __shared__ __align__(16) float Xs[32][EMB];
    const int r0 = blockIdx.x * 32;
    {
        const float4* xg = (const float4*)(X + (size_t)r0 * EMB);
        float4* xs = (float4*)&Xs[0][0];
        #pragma unroll
        for (int i = 0; i < 4; i++)
            xs[threadIdx.x + 256 * i] = xg[threadIdx.x + 256 * i];
    }
    __syncthreads();

    const int oc = threadIdx.x & 31;
    const int c4 = oc * 4;
    const int rg = threadIdx.x >> 5;

    float aq[4][4], ak[4][4], av[4][4];
    #pragma unroll
    for (int i = 0; i < 4; i++)
        #pragma unroll
        for (int j = 0; j < 4; j++) { aq[i][j] = 0.f; ak[i][j] = 0.f; av[i][j] = 0.f; }

    for (int e0 = 0; e0 < EMB; e0 += 4) {
        float4 xr[4];
        #pragma unroll
        for (int i = 0; i < 4; i++)
            xr[i] = *(const float4*)&Xs[rg * 4 + i][e0];
        #pragma unroll
        for (int ee = 0; ee < 4; ee++) {
            const int e = e0 + ee;
            float4 wq = *(const float4*)(Wq + e * EMB + c4);
            float4 wk = *(const float4*)(Wk + e * EMB + c4);
            float4 wv = *(const float4*)(Wv + e * EMB + c4);
            #pragma unroll
            for (int i = 0; i < 4; i++) {
                float x = (ee == 0) ? xr[i].x : (ee == 1) ? xr[i].y
                        : (ee == 2) ? xr[i].z : xr[i].w;
                aq[i][0] += x * wq.x; aq[i][1] += x * wq.y;
                aq[i][2] += x * wq.z; aq[i][3] += x * wq.w;
                ak[i][0] += x * wk.x; ak[i][1] += x * wk.y;
                ak[i][2] += x * wk.z; ak[i][3] += x * wk.w;
                av[i][0] += x * wv.x; av[i][1] += x * wv.y;
                av[i][2] += x * wv.z; av[i][3] += x * wv.w;
            }
        }
    }

    #pragma unroll
    for (int i = 0; i < 4; i++) {
        const int r = r0 + rg * 4 + i;
        const int b = r >> 11;
        const int s = r & (SEQ - 1);
        #pragma unroll
        for (int j = 0; j < 4; j++) {
            const int c = c4 + j;
            const int h = c & 7;
            const int d = c >> 3;
            const int idx = (((b * NH + h) * SEQ + s) * HD) + d;
            g_Q[idx] = aq[i][j];
            g_K[idx] = ak[i][j];
            g_V[idx] = av[i][j];
        }
    }
}

// ---------------------------------------------------------------------------
// Kernel 2: flash attention partial. Head-dim split + 4 queries/lane.
// Grid (SEQ/128, BATCH*NH, NKV) = (16,16,4), 64 threads (2 warps).
// Lane l: dh = l>>4 owns head dims [dh*8, dh*8+8); ql = l&15 owns queries
// qbase..qbase+3. Per key: each lane loads only its 32B K/V half; partial
// QK dots completed by one shfl.xor(16). Both dh lanes compute identical
// (m, l) so no cross-dh softmax merge is needed; each writes its acc half.
// CTA z handles keys [z*512, z*512+512); combine_kernel merges the 4 splits.
// ---------------------------------------------------------------------------
__global__ __launch_bounds__(64, 8) void attn_kernel(
    const int* __restrict__ mask_src)
{
    __shared__ __align__(16) float Ks[KT * HD];
    __shared__ __align__(16) float Vs[KT * HD];
    __shared__ float addm[KT];

    const int tid  = threadIdx.x;
    const int w    = tid >> 5;
    const int lane = tid & 31;
    const int dh   = lane >> 4;          // 0/1: head-dim half
    const int ql   = lane & 15;
    const int bh   = blockIdx.y;
    const int b    = bh >> 3;
    const int z    = blockIdx.z;
    const int qbase = blockIdx.x * 128 + w * 64 + ql * 4;

    const float* Qb = g_Q + (size_t)bh * SEQ * HD;
    const float* Kb = g_K + (size_t)bh * SEQ * HD;
    const float* Vb = g_V + (size_t)bh * SEQ * HD;

    // q halves, scaled by log2(e)/sqrt(HD)
    u64 qh[4][4];
    {
        const float SC = 0.3606737602222409f;  // 1.4426950408889634 / 4
        #pragma unroll
        for (int qi = 0; qi < 4; qi++) {
            const float4* qp = (const float4*)(Qb + (qbase + qi) * HD + dh * 8);
            float4 v0 = qp[0], v1 = qp[1];
            qh[qi][0] = pack2(v0.x * SC, v0.y * SC);
            qh[qi][1] = pack2(v0.z * SC, v0.w * SC);
            qh[qi][2] = pack2(v1.x * SC, v1.y * SC);
            qh[qi][3] = pack2(v1.z * SC, v1.w * SC);
        }
    }

    float m[4], l[4];
    u64 acc[4][4];
    #pragma unroll
    for (int qi = 0; qi < 4; qi++) {
        m[qi] = -1e30f;  l[qi] = 0.f;
        #pragma unroll
        for (int j = 0; j < 4; j++) acc[qi][j] = pack2(0.f, 0.f);
    }

    const float NEGM = -1442.6950408889634f;  // -1000 * log2(e)

    const int kb0 = z * KEYS_PER_CTA;
    for (int kb = kb0; kb < kb0 + KEYS_PER_CTA; kb += KT) {
        __syncthreads();
        {
            const float4* kg = (const float4*)(Kb + kb * HD);
            const float4* vg = (const float4*)(Vb + kb * HD);
            float4* ks4 = (float4*)Ks;
            float4* vs4 = (float4*)Vs;
            #pragma unroll
            for (int i = 0; i < 8; i++) {
                const int idx = tid + 64 * i;       // 512 float4 total
                ks4[idx] = kg[idx];
                vs4[idx] = vg[idx];
            }
            addm[tid]      = mask_src[b * SEQ + kb + tid]      ? 0.f : NEGM;
            addm[tid + 64] = mask_src[b * SEQ + kb + tid + 64] ? 0.f : NEGM;
        }
        __syncthreads();

        #pragma unroll 1
        for (int c = 0; c < KT; c += 4) {
            float s[4][4];
            float cm[4] = {-1e30f, -1e30f, -1e30f, -1e30f};

            // Pass 1: scores for 4 keys x 4 queries
            #pragma unroll
            for (int kk = 0; kk < 4; kk++) {
                const int key = c + kk;
                const double2* kr = (const double2*)(Ks + key * HD + dh * 8);
                double2 d0 = kr[0], d1 = kr[1];
                const u64 k0 = __double_as_longlong(d0.x);
                const u64 k1 = __double_as_longlong(d0.y);
                const u64 k2 = __double_as_longlong(d1.x);
                const u64 k3 = __double_as_longlong(d1.y);
                const float am = addm[key];
                #pragma unroll
                for (int qi = 0; qi < 4; qi++) {
                    u64 t = mul2(qh[qi][0], k0);
                    t = fma2(qh[qi][1], k1, t);
                    t = fma2(qh[qi][2], k2, t);
                    t = fma2(qh[qi][3], k3, t);
                    float ta, tb; unpack2(t, ta, tb);
                    const float ps   = ta + tb;
                    const float full = ps + __shfl_xor_sync(0xFFFFFFFFu, ps, 16);
                    const float sv   = full + am;
                    s[kk][qi] = sv;
                    cm[qi] = fmaxf(cm[qi], sv);
                }
            }

            // Rescale only when some lane's running max changed.
            const bool upd = (cm[0] > m[0]) | (cm[1] > m[1]) |
                             (cm[2] > m[2]) | (cm[3] > m[3]);
            if (__any_sync(0xFFFFFFFFu, upd)) {
                #pragma unroll
                for (int qi = 0; qi < 4; qi++) {
                    const float nm = fmaxf(m[qi], cm[qi]);
                    const float co = ex2f(m[qi] - nm);
                    l[qi] *= co;  m[qi] = nm;
                    const u64 c2 = pack2(co, co);
                    acc[qi][0] = mul2(acc[qi][0], c2);
                    acc[qi][1] = mul2(acc[qi][1], c2);
                    acc[qi][2] = mul2(acc[qi][2], c2);
                    acc[qi][3] = mul2(acc[qi][3], c2);
                }
            }

            // Pass 2: exp + PV accumulate
            #pragma unroll
            for (int kk = 0; kk < 4; kk++) {
                const int key = c + kk;
                const double2* vr = (const double2*)(Vs + key * HD + dh * 8);
                double2 d0 = vr[0], d1 = vr[1];
                const u64 v0 = __double_as_longlong(d0.x);
                const u64 v1 = __double_as_longlong(d0.y);
                const u64 v2 = __double_as_longlong(d1.x);
                const u64 v3 = __double_as_longlong(d1.y);
                #pragma unroll
                for (int qi = 0; qi < 4; qi++) {
                    const float p = ex2f(s[kk][qi] - m[qi]);
                    l[qi] += p;
                    const u64 pp = pack2(p, p);
                    acc[qi][0] = fma2(pp, v0, acc[qi][0]);
                    acc[qi][1] = fma2(pp, v1, acc[qi][1]);
                    acc[qi][2] = fma2(pp, v2, acc[qi][2]);
                    acc[qi][3] = fma2(pp, v3, acc[qi][3]);
                }
            }
        }
    }

    // Write partial records: each dh lane writes its 8-dim half; dh==0 writes (m,l).
    #pragma unroll
    for (int qi = 0; qi < 4; qi++) {
        float f[8];
        #pragma unroll
        for (int j = 0; j < 4; j++) unpack2(acc[qi][j], f[2*j], f[2*j+1]);
        float* pr = g_part + ((size_t)(bh * SEQ + qbase + qi) * NKV + z) * PREC;
        *(float4*)(pr + dh * 8)     = make_float4(f[0], f[1], f[2], f[3]);
        *(float4*)(pr + dh * 8 + 4) = make_float4(f[4], f[5], f[6], f[7]);
        if (dh == 0) { pr[16] = m[qi]; pr[17] = l[qi]; }
    }
}

// ---------------------------------------------------------------------------
// Kernel 3: merge NKV partials per query row, write final output.
// One thread per query row (32768 threads).
// ---------------------------------------------------------------------------
__global__ __launch_bounds__(128) void combine_kernel(float* __restrict__ out)
{
    const int idx = blockIdx.x * 128 + threadIdx.x;   // 0..32767: bh*SEQ + q
    const float* p = g_part + (size_t)idx * NKV * PREC;

    float4 t0 = *(const float4*)(p + 16);
    float4 t1 = *(const float4*)(p + PREC + 16);
    float4 t2 = *(const float4*)(p + 2*PREC + 16);
    float4 t3 = *(const float4*)(p + 3*PREC + 16);
    const float M = fmaxf(fmaxf(t0.x, t1.x), fmaxf(t2.x, t3.x));
    const float w0 = ex2f(t0.x - M), w1 = ex2f(t1.x - M);
    const float w2 = ex2f(t2.x - M), w3 = ex2f(t3.x - M);
    const float denom = t0.y * w0 + t1.y * w1 + t2.y * w2 + t3.y * w3;
    const float inv = 1.f / denom;

    const int bh = idx >> 11;            // / SEQ
    const int q  = idx & (SEQ - 1);
    const int b  = bh >> 3;
    const int h  = bh & 7;
    float* op = out + ((size_t)(b * SEQ + q)) * EMB + h;

    #pragma unroll
    for (int i = 0; i < 4; i++) {
        float4 a0 = *(const float4*)(p + 4 * i);
        float4 a1 = *(const float4*)(p + PREC + 4 * i);
        float4 a2 = *(const float4*)(p + 2*PREC + 4 * i);
        float4 a3 = *(const float4*)(p + 3*PREC + 4 * i);
        op[(4*i+0) * NH] = (a0.x*w0 + a1.x*w1 + a2.x*w2 + a3.x*w3) * inv;
        op[(4*i+1) * NH] = (a0.y*w0 + a1.y*w1 + a2.y*w2 + a3.y*w3) * inv;
        op[(4*i+2) * NH] = (a0.z*w0 + a1.z*w1 + a2.z*w2 + a3.z*w3) * inv;
        op[(4*i+3) * NH] = (a0.w*w0 + a1.w*w1 + a2.w*w2 + a3.w*w3) * inv;
    }
}

extern "C" void kernel_launch(void* const* d_in, const int* in_sizes, int n_in,
                              void* d_out, int out_size)
{
    const float* X    = (const float*)d_in[0];
    const int*   msk  = (const int*)d_in[1];
    // d_in[2] = target mask (unused, encoder path), d_in[3] = masked flag (0)
    const float* Wq   = (const float*)d_in[4];
    const float* Wk   = (const float*)d_in[5];
    const float* Wv   = (const float*)d_in[6];
    float* out        = (float*)d_out;

    qkv_kernel<<<NROWS / 32, 256>>>(X, Wq, Wk, Wv);

    dim3 grid(SEQ / 128, BATCH * NH, NKV);
    attn_kernel<<<grid, 64>>>(msk);

    combine_kernel<<<BATCH * NH * SEQ / 128, 128>>>(out);
}

// round 7
// speedup vs baseline: 1.0899x; 1.0899x over previous
#include <cuda_runtime.h>

#define BATCH 2
#define SEQ   2048
#define EMB   128
#define NH    8
#define HD    16
#define NROWS (BATCH*SEQ)
#define KT    128        // keys per smem tile
#define NKV   4          // KV splits across CTAs
#define KEYS_PER_CTA (SEQ/NKV)   // 512
#define PREC  20         // floats per partial record (16 acc, m, l, pad)
#define QROWS 16         // rows per qkv CTA

// Scratch for head-split Q/K/V in [b][h][s][d] layout (d contiguous, 64B rows).
__device__ float g_Q[BATCH*NH*SEQ*HD];
__device__ float g_K[BATCH*NH*SEQ*HD];
__device__ float g_V[BATCH*NH*SEQ*HD];
// Partials: [query_row(32768)][kv_split(4)][PREC]
__device__ float g_part[BATCH*NH*SEQ*NKV*PREC];

typedef unsigned long long u64;

__device__ __forceinline__ u64 pack2(float lo, float hi){
    u64 r; asm("mov.b64 %0, {%1, %2};" : "=l"(r) : "f"(lo), "f"(hi)); return r;
}
__device__ __forceinline__ void unpack2(u64 v, float& a, float& b){
    asm("mov.b64 {%0, %1}, %2;" : "=f"(a), "=f"(b) : "l"(v));
}
__device__ __forceinline__ u64 fma2(u64 a, u64 b, u64 c){
    u64 d; asm("fma.rn.f32x2 %0, %1, %2, %3;" : "=l"(d) : "l"(a), "l"(b), "l"(c)); return d;
}
__device__ __forceinline__ u64 mul2(u64 a, u64 b){
    u64 d; asm("mul.rn.f32x2 %0, %1, %2;" : "=l"(d) : "l"(a), "l"(b)); return d;
}
__device__ __forceinline__ float ex2f(float x){
    float y; asm("ex2.approx.ftz.f32 %0, %1;" : "=f"(y) : "f"(x)); return y;
}

// ---------------------------------------------------------------------------
// Kernel 1: fused QKV projection + head split, f32x2 version.
// Grid 256 CTAs (16 rows each), 256 threads. Thread = 2 rows x 4 cols x 3 mats
// with packed f32x2 accumulators (12 u64). W rows loaded as double2 (16B).
// ---------------------------------------------------------------------------
__global__ __launch_bounds__(256) void qkv_kernel(
    const float* __restrict__ X,
    const float* __restrict__ Wq, const float* __restrict__ Wk,
    const float* __restrict__ Wv)
{
    __shared__ __align__(16) float Xs[QROWS][EMB];
    const int tid = threadIdx.x;
    const int r0 = blockIdx.x * QROWS;
    {
        const float4* xg = (const float4*)(X + (size_t)r0 * EMB);
        float4* xs = (float4*)&Xs[0][0];
        #pragma unroll
        for (int i = 0; i < 2; i++)
            xs[tid + 256 * i] = xg[tid + 256 * i];
    }
    __syncthreads();

    const int oc = tid & 31;
    const int c4 = oc * 4;
    const int rg = tid >> 5;              // 0..7 -> rows rg*2, rg*2+1

    // acc[row][mat*2 + pair]: mats q,k,v; pairs (c4,c4+1),(c4+2,c4+3)
    u64 acc[2][6];
    #pragma unroll
    for (int i = 0; i < 2; i++)
        #pragma unroll
        for (int j = 0; j < 6; j++) acc[i][j] = pack2(0.f, 0.f);

    for (int e0 = 0; e0 < EMB; e0 += 4) {
        float4 x0 = *(const float4*)&Xs[rg * 2][e0];
        float4 x1 = *(const float4*)&Xs[rg * 2 + 1][e0];
        #pragma unroll
        for (int ee = 0; ee < 4; ee++) {
            const int e = e0 + ee;
            const float xa = (ee == 0) ? x0.x : (ee == 1) ? x0.y : (ee == 2) ? x0.z : x0.w;
            const float xb = (ee == 0) ? x1.x : (ee == 1) ? x1.y : (ee == 2) ? x1.z : x1.w;
            const u64 xa2 = pack2(xa, xa);
            const u64 xb2 = pack2(xb, xb);
            const double2 wq = *(const double2*)(Wq + e * EMB + c4);
            const double2 wk = *(const double2*)(Wk + e * EMB + c4);
            const double2 wv = *(const double2*)(Wv + e * EMB + c4);
            const u64 q0 = __double_as_longlong(wq.x), q1 = __double_as_longlong(wq.y);
            const u64 k0 = __double_as_longlong(wk.x), k1 = __double_as_longlong(wk.y);
            const u64 v0 = __double_as_longlong(wv.x), v1 = __double_as_longlong(wv.y);
            acc[0][0] = fma2(xa2, q0, acc[0][0]);  acc[0][1] = fma2(xa2, q1, acc[0][1]);
            acc[0][2] = fma2(xa2, k0, acc[0][2]);  acc[0][3] = fma2(xa2, k1, acc[0][3]);
            acc[0][4] = fma2(xa2, v0, acc[0][4]);  acc[0][5] = fma2(xa2, v1, acc[0][5]);
            acc[1][0] = fma2(xb2, q0, acc[1][0]);  acc[1][1] = fma2(xb2, q1, acc[1][1]);
            acc[1][2] = fma2(xb2, k0, acc[1][2]);  acc[1][3] = fma2(xb2, k1, acc[1][3]);
            acc[1][4] = fma2(xb2, v0, acc[1][4]);  acc[1][5] = fma2(xb2, v1, acc[1][5]);
        }
    }

    #pragma unroll
    for (int i = 0; i < 2; i++) {
        const int r = r0 + rg * 2 + i;
        const int b = r >> 11;            // r / SEQ
        const int s = r & (SEQ - 1);      // r % SEQ
        float fq[4], fk[4], fv[4];
        unpack2(acc[i][0], fq[0], fq[1]);  unpack2(acc[i][1], fq[2], fq[3]);
        unpack2(acc[i][2], fk[0], fk[1]);  unpack2(acc[i][3], fk[2], fk[3]);
        unpack2(acc[i][4], fv[0], fv[1]);  unpack2(acc[i][5], fv[2], fv[3]);
        #pragma unroll
        for (int j = 0; j < 4; j++) {
            const int c = c4 + j;
            const int h = c & 7;
            const int d = c >> 3;
            const int idx = (((b * NH + h) * SEQ + s) * HD) + d;
            g_Q[idx] = fq[j];
            g_K[idx] = fk[j];
            g_V[idx] = fv[j];
        }
    }
}

// ---------------------------------------------------------------------------
// Kernel 2: flash attention partial (R5 structure, 128-reg launch bounds).
// 2 queries/thread, 4-way lane KV split, 4-way CTA KV split.
// Grid (32, 16, 4), 128 threads (4 warps).
// ---------------------------------------------------------------------------
#define KROW  20         // padded floats per K/V smem row (80B, conflict-free 4-way split)

__global__ __launch_bounds__(128, 4) void attn_kernel(
    const int* __restrict__ mask_src)
{
    __shared__ __align__(16) float Ks[KT * KROW];
    __shared__ __align__(16) float Vs[KT * KROW];
    __shared__ float addm[KT];

    const int tid  = threadIdx.x;
    const int w    = tid >> 5;
    const int lane = tid & 31;
    const int spl  = lane >> 3;          // 0..3 (in-warp key split)
    const int bh   = blockIdx.y;
    const int b    = bh >> 3;
    const int z    = blockIdx.z;         // CTA KV split 0..3
    const int qA = blockIdx.x * 64 + w * 16 + (lane & 7) * 2;
    const int qB = qA + 1;

    const float* Qb = g_Q + (size_t)bh * SEQ * HD;
    const float* Kb = g_K + (size_t)bh * SEQ * HD;
    const float* Vb = g_V + (size_t)bh * SEQ * HD;

    // q scaled by log2(e)/sqrt(HD)
    u64 qa2[8], qb2[8];
    {
        const float SC = 0.3606737602222409f;  // 1.4426950408889634 / 4
        const float4* pa = (const float4*)(Qb + qA * HD);
        const float4* pb = (const float4*)(Qb + qB * HD);
        #pragma unroll
        for (int i = 0; i < 4; i++) {
            float4 va = pa[i], vb = pb[i];
            qa2[2*i]   = pack2(va.x * SC, va.y * SC);
            qa2[2*i+1] = pack2(va.z * SC, va.w * SC);
            qb2[2*i]   = pack2(vb.x * SC, vb.y * SC);
            qb2[2*i+1] = pack2(vb.z * SC, vb.w * SC);
        }
    }

    float mA = -1e30f, lA = 0.f, mB = -1e30f, lB = 0.f;
    u64 accA[8], accB[8];
    #pragma unroll
    for (int i = 0; i < 8; i++) { accA[i] = pack2(0.f, 0.f); accB[i] = pack2(0.f, 0.f); }

    const float NEGM = -1442.6950408889634f;  // -1000 * log2(e)

    const int kb0 = z * KEYS_PER_CTA;
    for (int kb = kb0; kb < kb0 + KEYS_PER_CTA; kb += KT) {
        __syncthreads();
        {
            const float4* kg = (const float4*)(Kb + kb * HD);
            const float4* vg = (const float4*)(Vb + kb * HD);
            #pragma unroll
            for (int i = 0; i < 4; i++) {
                const int idx = tid + 128 * i;      // float4 index, 512 total
                const int row = idx >> 2;
                const int c4  = (idx & 3) * 4;
                *(float4*)&Ks[row * KROW + c4] = kg[idx];
                *(float4*)&Vs[row * KROW + c4] = vg[idx];
            }
            addm[tid] = mask_src[b * SEQ + kb + tid] ? 0.f : NEGM;
        }
        __syncthreads();

        // This split's keys: local index 4*j + spl, j in [0,32), chunks of 8.
        #pragma unroll
        for (int c = 0; c < 32; c += 8) {
            float sA[8], sB[8];
            float cmA = -1e30f, cmB = -1e30f;
            #pragma unroll
            for (int kk = 0; kk < 8; kk++) {
                const int krow = ((c + kk) << 2) + spl;
                const double2* kr = (const double2*)(Ks + krow * KROW);
                double2 p0 = kr[0], p1 = kr[1], p2 = kr[2], p3 = kr[3];
                const u64 k0 = __double_as_longlong(p0.x), k1 = __double_as_longlong(p0.y);
                const u64 k2 = __double_as_longlong(p1.x), k3 = __double_as_longlong(p1.y);
                const u64 k4 = __double_as_longlong(p2.x), k5 = __double_as_longlong(p2.y);
                const u64 k6 = __double_as_longlong(p3.x), k7 = __double_as_longlong(p3.y);
                u64 tA = mul2(qa2[0], k0);
                u64 tB = mul2(qb2[0], k0);
                tA = fma2(qa2[1], k1, tA);  tB = fma2(qb2[1], k1, tB);
                tA = fma2(qa2[2], k2, tA);  tB = fma2(qb2[2], k2, tB);
                tA = fma2(qa2[3], k3, tA);  tB = fma2(qb2[3], k3, tB);
                tA = fma2(qa2[4], k4, tA);  tB = fma2(qb2[4], k4, tB);
                tA = fma2(qa2[5], k5, tA);  tB = fma2(qb2[5], k5, tB);
                tA = fma2(qa2[6], k6, tA);  tB = fma2(qb2[6], k6, tB);
                tA = fma2(qa2[7], k7, tA);  tB = fma2(qb2[7], k7, tB);
                const float am = addm[krow];
                float ta0, ta1, tb0, tb1;
                unpack2(tA, ta0, ta1);
                unpack2(tB, tb0, tb1);
                const float svA = ta0 + ta1 + am;
                const float svB = tb0 + tb1 + am;
                sA[kk] = svA;  cmA = fmaxf(cmA, svA);
                sB[kk] = svB;  cmB = fmaxf(cmB, svB);
            }
            // Only rescale when some lane's running max changed.
            const bool upd = (cmA > mA) || (cmB > mB);
            if (__any_sync(0xFFFFFFFFu, upd)) {
                const float nmA = fmaxf(mA, cmA);
                const float coA = ex2f(mA - nmA);
                lA *= coA;  mA = nmA;
                const u64 cA2 = pack2(coA, coA);
                const float nmB = fmaxf(mB, cmB);
                const float coB = ex2f(mB - nmB);
                lB *= coB;  mB = nmB;
                const u64 cB2 = pack2(coB, coB);
                #pragma unroll
                for (int i = 0; i < 8; i++) {
                    accA[i] = mul2(accA[i], cA2);
                    accB[i] = mul2(accB[i], cB2);
                }
            }
            #pragma unroll
            for (int kk = 0; kk < 8; kk++) {
                const float pA = ex2f(sA[kk] - mA);
                const float pB = ex2f(sB[kk] - mB);
                lA += pA;  lB += pB;
                const u64 ppA = pack2(pA, pA);
                const u64 ppB = pack2(pB, pB);
                const int krow = ((c + kk) << 2) + spl;
                const double2* vr = (const double2*)(Vs + krow * KROW);
                double2 v0 = vr[0], v1 = vr[1], v2 = vr[2], v3 = vr[3];
                const u64 w0 = __double_as_longlong(v0.x), w1 = __double_as_longlong(v0.y);
                const u64 w2 = __double_as_longlong(v1.x), w3 = __double_as_longlong(v1.y);
                const u64 w4 = __double_as_longlong(v2.x), w5 = __double_as_longlong(v2.y);
                const u64 w6 = __double_as_longlong(v3.x), w7 = __double_as_longlong(v3.y);
                accA[0] = fma2(ppA, w0, accA[0]);  accB[0] = fma2(ppB, w0, accB[0]);
                accA[1] = fma2(ppA, w1, accA[1]);  accB[1] = fma2(ppB, w1, accB[1]);
                accA[2] = fma2(ppA, w2, accA[2]);  accB[2] = fma2(ppB, w2, accB[2]);
                accA[3] = fma2(ppA, w3, accA[3]);  accB[3] = fma2(ppB, w3, accB[3]);
                accA[4] = fma2(ppA, w4, accA[4]);  accB[4] = fma2(ppB, w4, accB[4]);
                accA[5] = fma2(ppA, w5, accA[5]);  accB[5] = fma2(ppB, w5, accB[5]);
                accA[6] = fma2(ppA, w6, accA[6]);  accB[6] = fma2(ppB, w6, accB[6]);
                accA[7] = fma2(ppA, w7, accA[7]);  accB[7] = fma2(ppB, w7, accB[7]);
            }
        }
    }

    // Merge the 4 in-warp lane splits via 2 butterfly shfl rounds.
    float fA[16], fB[16];
    #pragma unroll
    for (int i = 0; i < 8; i++) {
        unpack2(accA[i], fA[2*i], fA[2*i+1]);
        unpack2(accB[i], fB[2*i], fB[2*i+1]);
    }

    #pragma unroll
    for (int off = 8; off <= 16; off <<= 1) {
        {
            const float mo = __shfl_xor_sync(0xFFFFFFFFu, mA, off);
            const float M  = fmaxf(mA, mo);
            const float c  = ex2f(mA - M);
            mA = M;  lA *= c;
            lA += __shfl_xor_sync(0xFFFFFFFFu, lA, off);
            #pragma unroll
            for (int i = 0; i < 16; i++) {
                fA[i] *= c;
                fA[i] += __shfl_xor_sync(0xFFFFFFFFu, fA[i], off);
            }
        }
        {
            const float mo = __shfl_xor_sync(0xFFFFFFFFu, mB, off);
            const float M  = fmaxf(mB, mo);
            const float c  = ex2f(mB - M);
            mB = M;  lB *= c;
            lB += __shfl_xor_sync(0xFFFFFFFFu, lB, off);
            #pragma unroll
            for (int i = 0; i < 16; i++) {
                fB[i] *= c;
                fB[i] += __shfl_xor_sync(0xFFFFFFFFu, fB[i], off);
            }
        }
    }

    // spl==0 lanes write the CTA-split partial records for qA and qB.
    if (spl == 0) {
        float* pa = g_part + ((size_t)(bh * SEQ + qA) * NKV + z) * PREC;
        float* pb = g_part + ((size_t)(bh * SEQ + qB) * NKV + z) * PREC;
        #pragma unroll
        for (int i = 0; i < 4; i++) {
            *(float4*)(pa + 4 * i) = make_float4(fA[4*i], fA[4*i+1], fA[4*i+2], fA[4*i+3]);
            *(float4*)(pb + 4 * i) = make_float4(fB[4*i], fB[4*i+1], fB[4*i+2], fB[4*i+3]);
        }
        *(float4*)(pa + 16) = make_float4(mA, lA, 0.f, 0.f);
        *(float4*)(pb + 16) = make_float4(mB, lB, 0.f, 0.f);
    }
}

// ---------------------------------------------------------------------------
// Kernel 3: merge NKV partials per query row, write final output.
// ---------------------------------------------------------------------------
__global__ __launch_bounds__(128) void combine_kernel(float* __restrict__ out)
{
    const int idx = blockIdx.x * 128 + threadIdx.x;   // 0..32767: bh*SEQ + q
    const float* p = g_part + (size_t)idx * NKV * PREC;

    float4 t0 = *(const float4*)(p + 16);
    float4 t1 = *(const float4*)(p + PREC + 16);
    float4 t2 = *(const float4*)(p + 2*PREC + 16);
    float4 t3 = *(const float4*)(p + 3*PREC + 16);
    const float M = fmaxf(fmaxf(t0.x, t1.x), fmaxf(t2.x, t3.x));
    const float w0 = ex2f(t0.x - M), w1 = ex2f(t1.x - M);
    const float w2 = ex2f(t2.x - M), w3 = ex2f(t3.x - M);
    const float denom = t0.y * w0 + t1.y * w1 + t2.y * w2 + t3.y * w3;
    const float inv = 1.f / denom;

    const int bh = idx >> 11;            // / SEQ
    const int q  = idx & (SEQ - 1);
    const int b  = bh >> 3;
    const int h  = bh & 7;
    float* op = out + ((size_t)(b * SEQ + q)) * EMB + h;

    #pragma unroll
    for (int i = 0; i < 4; i++) {
        float4 a0 = *(const float4*)(p + 4 * i);
        float4 a1 = *(const float4*)(p + PREC + 4 * i);
        float4 a2 = *(const float4*)(p + 2*PREC + 4 * i);
        float4 a3 = *(const float4*)(p + 3*PREC + 4 * i);
        op[(4*i+0) * NH] = (a0.x*w0 + a1.x*w1 + a2.x*w2 + a3.x*w3) * inv;
        op[(4*i+1) * NH] = (a0.y*w0 + a1.y*w1 + a2.y*w2 + a3.y*w3) * inv;
        op[(4*i+2) * NH] = (a0.z*w0 + a1.z*w1 + a2.z*w2 + a3.z*w3) * inv;
        op[(4*i+3) * NH] = (a0.w*w0 + a1.w*w1 + a2.w*w2 + a3.w*w3) * inv;
    }
}

extern "C" void kernel_launch(void* const* d_in, const int* in_sizes, int n_in,
                              void* d_out, int out_size)
{
    const float* X    = (const float*)d_in[0];
    const int*   msk  = (const int*)d_in[1];
    // d_in[2] = target mask (unused, encoder path), d_in[3] = masked flag (0)
    const float* Wq   = (const float*)d_in[4];
    const float* Wk   = (const float*)d_in[5];
    const float* Wv   = (const float*)d_in[6];
    float* out        = (float*)d_out;

    qkv_kernel<<<NROWS / QROWS, 256>>>(X, Wq, Wk, Wv);

    dim3 grid(SEQ / 64, BATCH * NH, NKV);
    attn_kernel<<<grid, 128>>>(msk);

    combine_kernel<<<BATCH * NH * SEQ / 128, 128>>>(out);
}

// round 8
// speedup vs baseline: 1.1210x; 1.0285x over previous
#include <cuda_runtime.h>

#define BATCH 2
#define SEQ   2048
#define EMB   128
#define NH    8
#define HD    16
#define NROWS (BATCH*SEQ)
#define KT    128        // keys per smem tile
#define NKV   4          // KV splits across CTAs
#define KEYS_PER_CTA (SEQ/NKV)   // 512
#define PREC  20         // floats per partial record (16 acc, m, l, pad)

// Scratch for head-split Q/K/V in [b][h][s][d] layout (d contiguous, 64B rows).
__device__ float g_Q[BATCH*NH*SEQ*HD];
__device__ float g_K[BATCH*NH*SEQ*HD];
__device__ float g_V[BATCH*NH*SEQ*HD];
// Partials: [query_row(32768)][kv_split(4)][PREC]
__device__ float g_part[BATCH*NH*SEQ*NKV*PREC];

typedef unsigned long long u64;

__device__ __forceinline__ u64 pack2(float lo, float hi){
    u64 r; asm("mov.b64 %0, {%1, %2};" : "=l"(r) : "f"(lo), "f"(hi)); return r;
}
__device__ __forceinline__ void unpack2(u64 v, float& a, float& b){
    asm("mov.b64 {%0, %1}, %2;" : "=f"(a), "=f"(b) : "l"(v));
}
__device__ __forceinline__ u64 fma2(u64 a, u64 b, u64 c){
    u64 d; asm("fma.rn.f32x2 %0, %1, %2, %3;" : "=l"(d) : "l"(a), "l"(b), "l"(c)); return d;
}
__device__ __forceinline__ u64 mul2(u64 a, u64 b){
    u64 d; asm("mul.rn.f32x2 %0, %1, %2;" : "=l"(d) : "l"(a), "l"(b)); return d;
}
__device__ __forceinline__ float ex2f(float x){
    float y; asm("ex2.approx.ftz.f32 %0, %1;" : "=f"(y) : "f"(x)); return y;
}

// ---------------------------------------------------------------------------
// Kernel 1: QKV projection + head split, one W matrix per CTA.
// Grid (NROWS/32, 3): blockIdx.y selects q/k/v. 256 threads.
// Thread = 4 rows x 4 cols of one matrix (R1-proven blocking, 1/3 the work).
// ---------------------------------------------------------------------------
__global__ __launch_bounds__(256) void qkv_kernel(
    const float* __restrict__ X,
    const float* __restrict__ Wq, const float* __restrict__ Wk,
    const float* __restrict__ Wv)
{
    __shared__ __align__(16) float Xs[32][EMB];
    const int tid = threadIdx.x;
    const int r0 = blockIdx.x * 32;
    const int mat = blockIdx.y;
    const float* __restrict__ W = (mat == 0) ? Wq : (mat == 1) ? Wk : Wv;
    float* __restrict__ dst = (mat == 0) ? g_Q : (mat == 1) ? g_K : g_V;

    {
        const float4* xg = (const float4*)(X + (size_t)r0 * EMB);
        float4* xs = (float4*)&Xs[0][0];
        #pragma unroll
        for (int i = 0; i < 4; i++)
            xs[tid + 256 * i] = xg[tid + 256 * i];
    }
    __syncthreads();

    const int oc = tid & 31;
    const int c4 = oc * 4;
    const int rg = tid >> 5;   // 0..7 -> rows rg*4 .. rg*4+3

    float a[4][4];
    #pragma unroll
    for (int i = 0; i < 4; i++)
        #pragma unroll
        for (int j = 0; j < 4; j++) a[i][j] = 0.f;

    #pragma unroll 2
    for (int e0 = 0; e0 < EMB; e0 += 4) {
        float4 xr[4];
        #pragma unroll
        for (int i = 0; i < 4; i++)
            xr[i] = *(const float4*)&Xs[rg * 4 + i][e0];
        #pragma unroll
        for (int ee = 0; ee < 4; ee++) {
            const float4 w = *(const float4*)(W + (e0 + ee) * EMB + c4);
            #pragma unroll
            for (int i = 0; i < 4; i++) {
                const float x = (ee == 0) ? xr[i].x : (ee == 1) ? xr[i].y
                              : (ee == 2) ? xr[i].z : xr[i].w;
                a[i][0] += x * w.x;
                a[i][1] += x * w.y;
                a[i][2] += x * w.z;
                a[i][3] += x * w.w;
            }
        }
    }

    #pragma unroll
    for (int i = 0; i < 4; i++) {
        const int r = r0 + rg * 4 + i;
        const int b = r >> 11;            // r / SEQ
        const int s = r & (SEQ - 1);      // r % SEQ
        #pragma unroll
        for (int j = 0; j < 4; j++) {
            const int c = c4 + j;
            const int h = c & 7;
            const int d = c >> 3;
            dst[(((b * NH + h) * SEQ + s) * HD) + d] = a[i][j];
        }
    }
}

// ---------------------------------------------------------------------------
// Kernel 2: flash attention partial (unchanged from R7 — the win).
// 2 queries/thread, 4-way lane KV split, 4-way CTA KV split.
// Grid (32, 16, 4), 128 threads (4 warps), 128 regs.
// ---------------------------------------------------------------------------
#define KROW  20         // padded floats per K/V smem row (80B, conflict-free 4-way split)

__global__ __launch_bounds__(128, 4) void attn_kernel(
    const int* __restrict__ mask_src)
{
    __shared__ __align__(16) float Ks[KT * KROW];
    __shared__ __align__(16) float Vs[KT * KROW];
    __shared__ float addm[KT];

    const int tid  = threadIdx.x;
    const int w    = tid >> 5;
    const int lane = tid & 31;
    const int spl  = lane >> 3;          // 0..3 (in-warp key split)
    const int bh   = blockIdx.y;
    const int b    = bh >> 3;
    const int z    = blockIdx.z;         // CTA KV split 0..3
    const int qA = blockIdx.x * 64 + w * 16 + (lane & 7) * 2;
    const int qB = qA + 1;

    const float* Qb = g_Q + (size_t)bh * SEQ * HD;
    const float* Kb = g_K + (size_t)bh * SEQ * HD;
    const float* Vb = g_V + (size_t)bh * SEQ * HD;

    // q scaled by log2(e)/sqrt(HD)
    u64 qa2[8], qb2[8];
    {
        const float SC = 0.3606737602222409f;  // 1.4426950408889634 / 4
        const float4* pa = (const float4*)(Qb + qA * HD);
        const float4* pb = (const float4*)(Qb + qB * HD);
        #pragma unroll
        for (int i = 0; i < 4; i++) {
            float4 va = pa[i], vb = pb[i];
            qa2[2*i]   = pack2(va.x * SC, va.y * SC);
            qa2[2*i+1] = pack2(va.z * SC, va.w * SC);
            qb2[2*i]   = pack2(vb.x * SC, vb.y * SC);
            qb2[2*i+1] = pack2(vb.z * SC, vb.w * SC);
        }
    }

    float mA = -1e30f, lA = 0.f, mB = -1e30f, lB = 0.f;
    u64 accA[8], accB[8];
    #pragma unroll
    for (int i = 0; i < 8; i++) { accA[i] = pack2(0.f, 0.f); accB[i] = pack2(0.f, 0.f); }

    const float NEGM = -1442.6950408889634f;  // -1000 * log2(e)

    const int kb0 = z * KEYS_PER_CTA;
    for (int kb = kb0; kb < kb0 + KEYS_PER_CTA; kb += KT) {
        __syncthreads();
        {
            const float4* kg = (const float4*)(Kb + kb * HD);
            const float4* vg = (const float4*)(Vb + kb * HD);
            #pragma unroll
            for (int i = 0; i < 4; i++) {
                const int idx = tid + 128 * i;      // float4 index, 512 total
                const int row = idx >> 2;
                const int c4  = (idx & 3) * 4;
                *(float4*)&Ks[row * KROW + c4] = kg[idx];
                *(float4*)&Vs[row * KROW + c4] = vg[idx];
            }
            addm[tid] = mask_src[b * SEQ + kb + tid] ? 0.f : NEGM;
        }
        __syncthreads();

        // This split's keys: local index 4*j + spl, j in [0,32), chunks of 8.
        #pragma unroll
        for (int c = 0; c < 32; c += 8) {
            float sA[8], sB[8];
            float cmA = -1e30f, cmB = -1e30f;
            #pragma unroll
            for (int kk = 0; kk < 8; kk++) {
                const int krow = ((c + kk) << 2) + spl;
                const double2* kr = (const double2*)(Ks + krow * KROW);
                double2 p0 = kr[0], p1 = kr[1], p2 = kr[2], p3 = kr[3];
                const u64 k0 = __double_as_longlong(p0.x), k1 = __double_as_longlong(p0.y);
                const u64 k2 = __double_as_longlong(p1.x), k3 = __double_as_longlong(p1.y);
                const u64 k4 = __double_as_longlong(p2.x), k5 = __double_as_longlong(p2.y);
                const u64 k6 = __double_as_longlong(p3.x), k7 = __double_as_longlong(p3.y);
                u64 tA = mul2(qa2[0], k0);
                u64 tB = mul2(qb2[0], k0);
                tA = fma2(qa2[1], k1, tA);  tB = fma2(qb2[1], k1, tB);
                tA = fma2(qa2[2], k2, tA);  tB = fma2(qb2[2], k2, tB);
                tA = fma2(qa2[3], k3, tA);  tB = fma2(qb2[3], k3, tB);
                tA = fma2(qa2[4], k4, tA);  tB = fma2(qb2[4], k4, tB);
                tA = fma2(qa2[5], k5, tA);  tB = fma2(qb2[5], k5, tB);
                tA = fma2(qa2[6], k6, tA);  tB = fma2(qb2[6], k6, tB);
                tA = fma2(qa2[7], k7, tA);  tB = fma2(qb2[7], k7, tB);
                const float am = addm[krow];
                float ta0, ta1, tb0, tb1;
                unpack2(tA, ta0, ta1);
                unpack2(tB, tb0, tb1);
                const float svA = ta0 + ta1 + am;
                const float svB = tb0 + tb1 + am;
                sA[kk] = svA;  cmA = fmaxf(cmA, svA);
                sB[kk] = svB;  cmB = fmaxf(cmB, svB);
            }
            // Only rescale when some lane's running max changed.
            const bool upd = (cmA > mA) || (cmB > mB);
            if (__any_sync(0xFFFFFFFFu, upd)) {
                const float nmA = fmaxf(mA, cmA);
                const float coA = ex2f(mA - nmA);
                lA *= coA;  mA = nmA;
                const u64 cA2 = pack2(coA, coA);
                const float nmB = fmaxf(mB, cmB);
                const float coB = ex2f(mB - nmB);
                lB *= coB;  mB = nmB;
                const u64 cB2 = pack2(coB, coB);
                #pragma unroll
                for (int i = 0; i < 8; i++) {
                    accA[i] = mul2(accA[i], cA2);
                    accB[i] = mul2(accB[i], cB2);
                }
            }
            #pragma unroll
            for (int kk = 0; kk < 8; kk++) {
                const float pA = ex2f(sA[kk] - mA);
                const float pB = ex2f(sB[kk] - mB);
                lA += pA;  lB += pB;
                const u64 ppA = pack2(pA, pA);
                const u64 ppB = pack2(pB, pB);
                const int krow = ((c + kk) << 2) + spl;
                const double2* vr = (const double2*)(Vs + krow * KROW);
                double2 v0 = vr[0], v1 = vr[1], v2 = vr[2], v3 = vr[3];
                const u64 w0 = __double_as_longlong(v0.x), w1 = __double_as_longlong(v0.y);
                const u64 w2 = __double_as_longlong(v1.x), w3 = __double_as_longlong(v1.y);
                const u64 w4 = __double_as_longlong(v2.x), w5 = __double_as_longlong(v2.y);
                const u64 w6 = __double_as_longlong(v3.x), w7 = __double_as_longlong(v3.y);
                accA[0] = fma2(ppA, w0, accA[0]);  accB[0] = fma2(ppB, w0, accB[0]);
                accA[1] = fma2(ppA, w1, accA[1]);  accB[1] = fma2(ppB, w1, accB[1]);
                accA[2] = fma2(ppA, w2, accA[2]);  accB[2] = fma2(ppB, w2, accB[2]);
                accA[3] = fma2(ppA, w3, accA[3]);  accB[3] = fma2(ppB, w3, accB[3]);
                accA[4] = fma2(ppA, w4, accA[4]);  accB[4] = fma2(ppB, w4, accB[4]);
                accA[5] = fma2(ppA, w5, accA[5]);  accB[5] = fma2(ppB, w5, accB[5]);
                accA[6] = fma2(ppA, w6, accA[6]);  accB[6] = fma2(ppB, w6, accB[6]);
                accA[7] = fma2(ppA, w7, accA[7]);  accB[7] = fma2(ppB, w7, accB[7]);
            }
        }
    }

    // Merge the 4 in-warp lane splits via 2 butterfly shfl rounds.
    float fA[16], fB[16];
    #pragma unroll
    for (int i = 0; i < 8; i++) {
        unpack2(accA[i], fA[2*i], fA[2*i+1]);
        unpack2(accB[i], fB[2*i], fB[2*i+1]);
    }

    #pragma unroll
    for (int off = 8; off <= 16; off <<= 1) {
        {
            const float mo = __shfl_xor_sync(0xFFFFFFFFu, mA, off);
            const float M  = fmaxf(mA, mo);
            const float c  = ex2f(mA - M);
            mA = M;  lA *= c;
            lA += __shfl_xor_sync(0xFFFFFFFFu, lA, off);
            #pragma unroll
            for (int i = 0; i < 16; i++) {
                fA[i] *= c;
                fA[i] += __shfl_xor_sync(0xFFFFFFFFu, fA[i], off);
            }
        }
        {
            const float mo = __shfl_xor_sync(0xFFFFFFFFu, mB, off);
            const float M  = fmaxf(mB, mo);
            const float c  = ex2f(mB - M);
            mB = M;  lB *= c;
            lB += __shfl_xor_sync(0xFFFFFFFFu, lB, off);
            #pragma unroll
            for (int i = 0; i < 16; i++) {
                fB[i] *= c;
                fB[i] += __shfl_xor_sync(0xFFFFFFFFu, fB[i], off);
            }
        }
    }

    // spl==0 lanes write the CTA-split partial records for qA and qB.
    if (spl == 0) {
        float* pa = g_part + ((size_t)(bh * SEQ + qA) * NKV + z) * PREC;
        float* pb = g_part + ((size_t)(bh * SEQ + qB) * NKV + z) * PREC;
        #pragma unroll
        for (int i = 0; i < 4; i++) {
            *(float4*)(pa + 4 * i) = make_float4(fA[4*i], fA[4*i+1], fA[4*i+2], fA[4*i+3]);
            *(float4*)(pb + 4 * i) = make_float4(fB[4*i], fB[4*i+1], fB[4*i+2], fB[4*i+3]);
        }
        *(float4*)(pa + 16) = make_float4(mA, lA, 0.f, 0.f);
        *(float4*)(pb + 16) = make_float4(mB, lB, 0.f, 0.f);
    }
}

// ---------------------------------------------------------------------------
// Kernel 3: merge NKV partials per query row, write final output.
// ---------------------------------------------------------------------------
__global__ __launch_bounds__(128) void combine_kernel(float* __restrict__ out)
{
    const int idx = blockIdx.x * 128 + threadIdx.x;   // 0..32767: bh*SEQ + q
    const float* p = g_part + (size_t)idx * NKV * PREC;

    float4 t0 = *(const float4*)(p + 16);
    float4 t1 = *(const float4*)(p + PREC + 16);
    float4 t2 = *(const float4*)(p + 2*PREC + 16);
    float4 t3 = *(const float4*)(p + 3*PREC + 16);
    const float M = fmaxf(fmaxf(t0.x, t1.x), fmaxf(t2.x, t3.x));
    const float w0 = ex2f(t0.x - M), w1 = ex2f(t1.x - M);
    const float w2 = ex2f(t2.x - M), w3 = ex2f(t3.x - M);
    const float denom = t0.y * w0 + t1.y * w1 + t2.y * w2 + t3.y * w3;
    const float inv = 1.f / denom;

    const int bh = idx >> 11;            // / SEQ
    const int q  = idx & (SEQ - 1);
    const int b  = bh >> 3;
    const int h  = bh & 7;
    float* op = out + ((size_t)(b * SEQ + q)) * EMB + h;

    #pragma unroll
    for (int i = 0; i < 4; i++) {
        float4 a0 = *(const float4*)(p + 4 * i);
        float4 a1 = *(const float4*)(p + PREC + 4 * i);
        float4 a2 = *(const float4*)(p + 2*PREC + 4 * i);
        float4 a3 = *(const float4*)(p + 3*PREC + 4 * i);
        op[(4*i+0) * NH] = (a0.x*w0 + a1.x*w1 + a2.x*w2 + a3.x*w3) * inv;
        op[(4*i+1) * NH] = (a0.y*w0 + a1.y*w1 + a2.y*w2 + a3.y*w3) * inv;
        op[(4*i+2) * NH] = (a0.z*w0 + a1.z*w1 + a2.z*w2 + a3.z*w3) * inv;
        op[(4*i+3) * NH] = (a0.w*w0 + a1.w*w1 + a2.w*w2 + a3.w*w3) * inv;
    }
}

extern "C" void kernel_launch(void* const* d_in, const int* in_sizes, int n_in,
                              void* d_out, int out_size)
{
    const float* X    = (const float*)d_in[0];
    const int*   msk  = (const int*)d_in[1];
    // d_in[2] = target mask (unused, encoder path), d_in[3] = masked flag (0)
    const float* Wq   = (const float*)d_in[4];
    const float* Wk   = (const float*)d_in[5];
    const float* Wv   = (const float*)d_in[6];
    float* out        = (float*)d_out;

    dim3 qgrid(NROWS / 32, 3);
    qkv_kernel<<<qgrid, 256>>>(X, Wq, Wk, Wv);

    dim3 grid(SEQ / 64, BATCH * NH, NKV);
    attn_kernel<<<grid, 128>>>(msk);

    combine_kernel<<<BATCH * NH * SEQ / 128, 128>>>(out);
}

// round 10
// speedup vs baseline: 1.9114x; 1.7050x over previous
#include <cuda_runtime.h>
#include <cstdint>

#define BATCH 2
#define SEQ   2048
#define EMB   128
#define NH    8
#define HD    16
#define NROWS (BATCH*SEQ)
#define KTILE 64
#define NTILES (SEQ/KTILE)
#define KPAD  24     // uint16 elems per K smem row (48B -> conflict-free b-frag loads)
#define VPAD  72     // uint16 elems per V^t smem row (144B -> conflict-free)

// Scratch: Q,K in [bh][s][d]; V TRANSPOSED: [bh][d][s]
__device__ float g_Q[BATCH*NH*SEQ*HD];
__device__ float g_K[BATCH*NH*SEQ*HD];
__device__ float g_Vt[BATCH*NH*HD*SEQ];

__device__ __forceinline__ float ex2f(float x){
    float y; asm("ex2.approx.ftz.f32 %0, %1;" : "=f"(y) : "f"(x)); return y;
}
// pack {low=even, high=odd} bf16x2
__device__ __forceinline__ uint32_t bf2(float even, float odd){
    uint32_t r;
    asm("cvt.rn.bf16x2.f32 %0, %1, %2;" : "=r"(r) : "f"(odd), "f"(even));
    return r;
}
__device__ __forceinline__ float bflo(uint32_t r){ return __uint_as_float(r << 16); }
__device__ __forceinline__ float bfhi(uint32_t r){ return __uint_as_float(r & 0xFFFF0000u); }

// m16n8k16 row.col bf16 -> f32 accumulate (documented fragment layouts, sm_80+)
__device__ __forceinline__ void mma16816(float c[4], const uint32_t a[4], const uint32_t b[2]){
    asm volatile(
        "mma.sync.aligned.m16n8k16.row.col.f32.bf16.bf16.f32 "
        "{%0,%1,%2,%3}, {%4,%5,%6,%7}, {%8,%9}, {%0,%1,%2,%3};\n"
        : "+f"(c[0]), "+f"(c[1]), "+f"(c[2]), "+f"(c[3])
        : "r"(a[0]), "r"(a[1]), "r"(a[2]), "r"(a[3]), "r"(b[0]), "r"(b[1]));
}

// ---------------------------------------------------------------------------
// Kernel 1: QKV projection + head split, one W matrix per CTA (R8 winner).
// V is written TRANSPOSED: g_Vt[bh][d][s].
// ---------------------------------------------------------------------------
__global__ __launch_bounds__(256) void qkv_kernel(
    const float* __restrict__ X,
    const float* __restrict__ Wq, const float* __restrict__ Wk,
    const float* __restrict__ Wv)
{
    __shared__ __align__(16) float Xs[32][EMB];
    const int tid = threadIdx.x;
    const int r0 = blockIdx.x * 32;
    const int mat = blockIdx.y;
    const float* __restrict__ W = (mat == 0) ? Wq : (mat == 1) ? Wk : Wv;

    {
        const float4* xg = (const float4*)(X + (size_t)r0 * EMB);
        float4* xs = (float4*)&Xs[0][0];
        #pragma unroll
        for (int i = 0; i < 4; i++)
            xs[tid + 256 * i] = xg[tid + 256 * i];
    }
    __syncthreads();

    const int oc = tid & 31;
    const int c4 = oc * 4;
    const int rg = tid >> 5;

    float a[4][4];
    #pragma unroll
    for (int i = 0; i < 4; i++)
        #pragma unroll
        for (int j = 0; j < 4; j++) a[i][j] = 0.f;

    #pragma unroll 2
    for (int e0 = 0; e0 < EMB; e0 += 4) {
        float4 xr[4];
        #pragma unroll
        for (int i = 0; i < 4; i++)
            xr[i] = *(const float4*)&Xs[rg * 4 + i][e0];
        #pragma unroll
        for (int ee = 0; ee < 4; ee++) {
            const float4 w = *(const float4*)(W + (e0 + ee) * EMB + c4);
            #pragma unroll
            for (int i = 0; i < 4; i++) {
                const float x = (ee == 0) ? xr[i].x : (ee == 1) ? xr[i].y
                              : (ee == 2) ? xr[i].z : xr[i].w;
                a[i][0] += x * w.x;
                a[i][1] += x * w.y;
                a[i][2] += x * w.z;
                a[i][3] += x * w.w;
            }
        }
    }

    #pragma unroll
    for (int i = 0; i < 4; i++) {
        const int r = r0 + rg * 4 + i;
        const int b = r >> 11;
        const int s = r & (SEQ - 1);
        #pragma unroll
        for (int j = 0; j < 4; j++) {
            const int c = c4 + j;
            const int h = c & 7;
            const int d = c >> 3;
            const int bh = b * NH + h;
            if (mat == 0)
                g_Q[((size_t)bh * SEQ + s) * HD + d] = a[i][j];
            else if (mat == 1)
                g_K[((size_t)bh * SEQ + s) * HD + d] = a[i][j];
            else
                g_Vt[((size_t)bh * HD + d) * SEQ + s] = a[i][j];
        }
    }
}

// ---------------------------------------------------------------------------
// Kernel 2: flash attention on tensor cores via mma.sync bf16 hi/lo split.
// Grid (32 q-tiles, 16 bh), 128 threads (4 warps). Warp = 16 queries.
// Fragment roles (PTX-documented): gq=lane>>2, tq=lane&3.
//   QK: A=Q (rows qb+gq, qb+gq+8), B=K^T n-tiles of 8 keys -> scores in C regs
//   P: repacked from score C regs directly into A regs (no smem round trip)
//   PV: B=V^t k-steps of 16 keys, O accumulated in C regs with per-row rescale
// ---------------------------------------------------------------------------
__global__ __launch_bounds__(128, 4) void attn_kernel(
    const int* __restrict__ mask_src, float* __restrict__ out)
{
    __shared__ __align__(16) uint16_t sKhi[KTILE * KPAD];
    __shared__ __align__(16) uint16_t sKlo[KTILE * KPAD];
    __shared__ __align__(16) uint16_t sVhi[16 * VPAD];
    __shared__ __align__(16) uint16_t sVlo[16 * VPAD];
    __shared__ float addm[KTILE];

    const int tid  = threadIdx.x;
    const int wid  = tid >> 5;
    const int lane = tid & 31;
    const int gq   = lane >> 2;
    const int tq   = lane & 3;
    const int bh   = blockIdx.y;
    const int b    = bh >> 3;
    const int h    = bh & 7;
    const int qb   = blockIdx.x * 64 + wid * 16;
    const int row0 = qb + gq;
    const int row1 = qb + gq + 8;

    // ---- persistent Q fragments (hi/lo), scaled by log2(e)/sqrt(HD) ----
    uint32_t qhi[4], qlo[4];
    {
        const float SC = 0.3606737602222409f;
        const float* q0p = g_Q + ((size_t)bh * SEQ + row0) * HD;
        const float* q1p = g_Q + ((size_t)bh * SEQ + row1) * HD;
        float2 x[4];
        x[0] = *(const float2*)(q0p + 2 * tq);
        x[1] = *(const float2*)(q1p + 2 * tq);
        x[2] = *(const float2*)(q0p + 2 * tq + 8);
        x[3] = *(const float2*)(q1p + 2 * tq + 8);
        #pragma unroll
        for (int i = 0; i < 4; i++) {
            const float e = x[i].x * SC, o = x[i].y * SC;
            const uint32_t hp = bf2(e, o);
            qhi[i] = hp;
            qlo[i] = bf2(e - bflo(hp), o - bfhi(hp));
        }
    }

    float m0 = -1e30f, m1 = -1e30f, l0 = 0.f, l1 = 0.f;
    float ocf[2][4];
    #pragma unroll
    for (int nv = 0; nv < 2; nv++)
        #pragma unroll
        for (int j = 0; j < 4; j++) ocf[nv][j] = 0.f;

    const float NEGM = -1442.6950408889634f;   // -1000 * log2(e)
    const int key  = tid >> 1, half = tid & 1; // K staging role
    const int dv   = tid >> 3, kg   = tid & 7; // V^t staging role

    for (int t = 0; t < NTILES; t++) {
        const int kb = t * KTILE;
        __syncthreads();
        // ---- stage K tile (hi/lo bf16, padded rows) ----
        {
            const float* kr = g_K + ((size_t)bh * SEQ + kb + key) * HD + half * 8;
            const float4 a = *(const float4*)kr;
            const float4 c = *(const float4*)(kr + 4);
            const float x[8] = {a.x, a.y, a.z, a.w, c.x, c.y, c.z, c.w};
            uint32_t hb[4], lb[4];
            #pragma unroll
            for (int j = 0; j < 4; j++) {
                const uint32_t hp = bf2(x[2*j], x[2*j+1]);
                hb[j] = hp;
                lb[j] = bf2(x[2*j] - bflo(hp), x[2*j+1] - bfhi(hp));
            }
            *(uint4*)&sKhi[key * KPAD + half * 8] = make_uint4(hb[0], hb[1], hb[2], hb[3]);
            *(uint4*)&sKlo[key * KPAD + half * 8] = make_uint4(lb[0], lb[1], lb[2], lb[3]);
        }
        // ---- stage V^t tile ----
        {
            const float* vr = g_Vt + ((size_t)bh * HD + dv) * SEQ + kb + kg * 8;
            const float4 a = *(const float4*)vr;
            const float4 c = *(const float4*)(vr + 4);
            const float x[8] = {a.x, a.y, a.z, a.w, c.x, c.y, c.z, c.w};
            uint32_t hb[4], lb[4];
            #pragma unroll
            for (int j = 0; j < 4; j++) {
                const uint32_t hp = bf2(x[2*j], x[2*j+1]);
                hb[j] = hp;
                lb[j] = bf2(x[2*j] - bflo(hp), x[2*j+1] - bfhi(hp));
            }
            *(uint4*)&sVhi[dv * VPAD + kg * 8] = make_uint4(hb[0], hb[1], hb[2], hb[3]);
            *(uint4*)&sVlo[dv * VPAD + kg * 8] = make_uint4(lb[0], lb[1], lb[2], lb[3]);
        }
        if (tid < KTILE)
            addm[tid] = mask_src[b * SEQ + kb + tid] ? 0.f : NEGM;
        __syncthreads();

        // ---- QK: scores for 8 n-tiles of 8 keys ----
        float s[8][4];
        float rm0 = -1e30f, rm1 = -1e30f;
        #pragma unroll
        for (int n = 0; n < 8; n++) {
            const int krow = n * 8 + gq;
            uint32_t kbh[2], kbl[2];
            kbh[0] = *(const uint32_t*)&sKhi[krow * KPAD + 2 * tq];
            kbh[1] = *(const uint32_t*)&sKhi[krow * KPAD + 2 * tq + 8];
            kbl[0] = *(const uint32_t*)&sKlo[krow * KPAD + 2 * tq];
            kbl[1] = *(const uint32_t*)&sKlo[krow * KPAD + 2 * tq + 8];
            float cc[4] = {0.f, 0.f, 0.f, 0.f};
            mma16816(cc, qhi, kbh);
            mma16816(cc, qhi, kbl);
            mma16816(cc, qlo, kbh);
            const float am0 = addm[n * 8 + 2 * tq];
            const float am1 = addm[n * 8 + 2 * tq + 1];
            s[n][0] = cc[0] + am0;  s[n][1] = cc[1] + am1;
            s[n][2] = cc[2] + am0;  s[n][3] = cc[3] + am1;
            rm0 = fmaxf(rm0, fmaxf(s[n][0], s[n][1]));
            rm1 = fmaxf(rm1, fmaxf(s[n][2], s[n][3]));
        }

        // ---- online softmax (row-wise; quad reduce) ----
        rm0 = fmaxf(rm0, __shfl_xor_sync(0xFFFFFFFFu, rm0, 1));
        rm0 = fmaxf(rm0, __shfl_xor_sync(0xFFFFFFFFu, rm0, 2));
        rm1 = fmaxf(rm1, __shfl_xor_sync(0xFFFFFFFFu, rm1, 1));
        rm1 = fmaxf(rm1, __shfl_xor_sync(0xFFFFFFFFu, rm1, 2));
        const float nm0 = fmaxf(m0, rm0);
        const float nm1 = fmaxf(m1, rm1);
        const float c0 = ex2f(m0 - nm0);
        const float c1 = ex2f(m1 - nm1);
        m0 = nm0; m1 = nm1;
        l0 *= c0; l1 *= c1;
        #pragma unroll
        for (int nv = 0; nv < 2; nv++) {
            ocf[nv][0] *= c0;  ocf[nv][1] *= c0;
            ocf[nv][2] *= c1;  ocf[nv][3] *= c1;
        }
        #pragma unroll
        for (int n = 0; n < 8; n++) {
            s[n][0] = ex2f(s[n][0] - m0);
            s[n][1] = ex2f(s[n][1] - m0);
            s[n][2] = ex2f(s[n][2] - m1);
            s[n][3] = ex2f(s[n][3] - m1);
            l0 += s[n][0] + s[n][1];
            l1 += s[n][2] + s[n][3];
        }

        // ---- PV: P repacked from score regs; 4 k-steps x 2 dim n-tiles ----
        #pragma unroll
        for (int ks = 0; ks < 4; ks++) {
            uint32_t pah[4], pal[4];
            {
                uint32_t hp;
                hp = bf2(s[2*ks][0], s[2*ks][1]);   pah[0] = hp;
                pal[0] = bf2(s[2*ks][0] - bflo(hp), s[2*ks][1] - bfhi(hp));
                hp = bf2(s[2*ks][2], s[2*ks][3]);   pah[1] = hp;
                pal[1] = bf2(s[2*ks][2] - bflo(hp), s[2*ks][3] - bfhi(hp));
                hp = bf2(s[2*ks+1][0], s[2*ks+1][1]); pah[2] = hp;
                pal[2] = bf2(s[2*ks+1][0] - bflo(hp), s[2*ks+1][1] - bfhi(hp));
                hp = bf2(s[2*ks+1][2], s[2*ks+1][3]); pah[3] = hp;
                pal[3] = bf2(s[2*ks+1][2] - bflo(hp), s[2*ks+1][3] - bfhi(hp));
            }
            #pragma unroll
            for (int nv = 0; nv < 2; nv++) {
                const int vrow = nv * 8 + gq;
                uint32_t vbh[2], vbl[2];
                vbh[0] = *(const uint32_t*)&sVhi[vrow * VPAD + 16 * ks + 2 * tq];
                vbh[1] = *(const uint32_t*)&sVhi[vrow * VPAD + 16 * ks + 2 * tq + 8];
                vbl[0] = *(const uint32_t*)&sVlo[vrow * VPAD + 16 * ks + 2 * tq];
                vbl[1] = *(const uint32_t*)&sVlo[vrow * VPAD + 16 * ks + 2 * tq + 8];
                mma16816(ocf[nv], pah, vbh);
                mma16816(ocf[nv], pah, vbl);
                mma16816(ocf[nv], pal, vbh);
            }
        }
    }

    // ---- finalize: quad-sum l, write output ----
    l0 += __shfl_xor_sync(0xFFFFFFFFu, l0, 1);
    l0 += __shfl_xor_sync(0xFFFFFFFFu, l0, 2);
    l1 += __shfl_xor_sync(0xFFFFFFFFu, l1, 1);
    l1 += __shfl_xor_sync(0xFFFFFFFFu, l1, 2);
    const float inv0 = 1.f / l0;
    const float inv1 = 1.f / l1;
    float* o0 = out + ((size_t)(b * SEQ + row0)) * EMB + h;
    float* o1 = out + ((size_t)(b * SEQ + row1)) * EMB + h;
    #pragma unroll
    for (int nv = 0; nv < 2; nv++) {
        const int d = nv * 8 + 2 * tq;
        o0[d * NH]       = ocf[nv][0] * inv0;
        o0[(d + 1) * NH] = ocf[nv][1] * inv0;
        o1[d * NH]       = ocf[nv][2] * inv1;
        o1[(d + 1) * NH] = ocf[nv][3] * inv1;
    }
}

extern "C" void kernel_launch(void* const* d_in, const int* in_sizes, int n_in,
                              void* d_out, int out_size)
{
    const float* X    = (const float*)d_in[0];
    const int*   msk  = (const int*)d_in[1];
    // d_in[2] = target mask (unused, encoder path), d_in[3] = masked flag (0)
    const float* Wq   = (const float*)d_in[4];
    const float* Wk   = (const float*)d_in[5];
    const float* Wv   = (const float*)d_in[6];
    float* out        = (float*)d_out;

    dim3 qgrid(NROWS / 32, 3);
    qkv_kernel<<<qgrid, 256>>>(X, Wq, Wk, Wv);

    dim3 agrid(SEQ / 64, BATCH * NH);
    attn_kernel<<<agrid, 128>>>(msk, out);
}